// round 1
// baseline (speedup 1.0000x reference)
#include <cuda_runtime.h>
#include <math.h>

// ---------------------------------------------------------------------------
// CompletionNet: 3x sparse conv (gather-GEMM) + BN + ELU, fp32, C=32.
//   conv1: kvol=27, conv2: kvol=8, conv3: kvol=27.  N = 500k voxels.
// Strategy: tiled gather-GEMM with packed f32x2 FMA (2 FMA/instr on sm_103a).
// BN stats via per-block reduction + atomics; BN+ELU as separate elementwise
// pass (kernel boundary provides the grid-wide sync for the reduction).
// ---------------------------------------------------------------------------

#define NMAX   500000
#define NELEM  (NMAX * 32)
#define MT     128          // voxels per block
#define SROW   132          // padded smem row stride (floats) for A tile
#define EPS    1e-5f

__device__ float g_bufA[NELEM];
__device__ float g_bufB[NELEM];
__device__ float g_stats[3 * 64];   // per layer: [0:32)=sum, [32:64)=sumsq

typedef unsigned long long u64;

__device__ __forceinline__ u64 pack2(float lo, float hi) {
    u64 r; asm("mov.b64 %0, {%1, %2};" : "=l"(r) : "f"(lo), "f"(hi)); return r;
}
__device__ __forceinline__ float2 unpack2(u64 v) {
    float2 r; asm("mov.b64 {%0, %1}, %2;" : "=f"(r.x), "=f"(r.y) : "l"(v)); return r;
}
// packed dual-FMA: d.lo += a.lo*b.lo ; d.hi += a.hi*b.hi
__device__ __forceinline__ void ffma2(u64& d, u64 a, u64 b) {
    asm("fma.rn.f32x2 %0, %1, %2, %0;" : "+l"(d) : "l"(a), "l"(b));
}

// ---------------------------------------------------------------------------
// Gather-GEMM conv: out[n, co] = sum_k sum_ci in[nmap[k,n], ci] * W[k, ci, co]
// Block tile: 128 voxels x 32 co. Thread (tx, my): tx in [0,16) owns co pair
// (2tx, 2tx+1); my in [0,16) owns voxels my*8 .. my*8+7.
// Accumulators are voxel-paired f32x2 (4 pairs x 2 co = 8 u64).
// Also accumulates per-channel sum/sumsq into stats[] for the following BN.
// ---------------------------------------------------------------------------
__global__ __launch_bounds__(256)
void conv_kernel(const float* __restrict__ in, const int* __restrict__ nmap,
                 const float* __restrict__ W, float* __restrict__ out,
                 float* __restrict__ stats, int kvol, int N)
{
    __shared__ float Asm[32 * SROW];   // gathered tile, transposed [ci][m]
    __shared__ float Wsm[1024];        // W[k] : [ci][co]
    __shared__ float Red[1024];        // stats reduction: [0:512) sum, [512:1024) sumsq

    const int tid = threadIdx.x;
    const int tx  = tid & 15;          // co pair index
    const int my  = tid >> 4;          // voxel group
    const int m0  = my * 8;
    const int mbase = blockIdx.x * MT;

    const int gs = tid & 127;          // gather: voxel slot
    const int gh = tid >> 7;           // gather: channel half (0 or 1)

    u64 acc[4][2];
#pragma unroll
    for (int p = 0; p < 4; ++p) { acc[p][0] = 0ull; acc[p][1] = 0ull; }

    for (int k = 0; k < kvol; ++k) {
        __syncthreads();   // previous iteration's readers done with Asm/Wsm

        // --- load W[k] (1024 floats, coalesced) ---
        ((float4*)Wsm)[tid] = ((const float4*)(W + k * 1024))[tid];

        // --- gather neighbor rows into transposed smem tile ---
        {
            const int m = mbase + gs;
            const int idx = (m < N) ? nmap[(size_t)k * N + m] : -1;
            if (idx >= 0) {
                const float4* src = (const float4*)(in + (size_t)idx * 32) + gh * 4;
#pragma unroll
                for (int q = 0; q < 4; ++q) {
                    float4 v = src[q];
                    int ci = gh * 16 + q * 4;
                    Asm[(ci + 0) * SROW + gs] = v.x;
                    Asm[(ci + 1) * SROW + gs] = v.y;
                    Asm[(ci + 2) * SROW + gs] = v.z;
                    Asm[(ci + 3) * SROW + gs] = v.w;
                }
            } else {
#pragma unroll
                for (int q = 0; q < 4; ++q) {
                    int ci = gh * 16 + q * 4;
                    Asm[(ci + 0) * SROW + gs] = 0.f;
                    Asm[(ci + 1) * SROW + gs] = 0.f;
                    Asm[(ci + 2) * SROW + gs] = 0.f;
                    Asm[(ci + 3) * SROW + gs] = 0.f;
                }
            }
        }
        __syncthreads();

        // --- 128x32x32 GEMM tile, packed f32x2 ---
#pragma unroll 4
        for (int ci = 0; ci < 32; ++ci) {
            float2 w = *(const float2*)(Wsm + ci * 32 + 2 * tx);
            u64 wd0 = pack2(w.x, w.x);
            u64 wd1 = pack2(w.y, w.y);
            const u64* arow = (const u64*)(Asm + ci * SROW + m0);
            u64 a0 = arow[0], a1 = arow[1], a2 = arow[2], a3 = arow[3];
            ffma2(acc[0][0], a0, wd0); ffma2(acc[0][1], a0, wd1);
            ffma2(acc[1][0], a1, wd0); ffma2(acc[1][1], a1, wd1);
            ffma2(acc[2][0], a2, wd0); ffma2(acc[2][1], a2, wd1);
            ffma2(acc[3][0], a3, wd0); ffma2(acc[3][1], a3, wd1);
        }
    }

    // --- store outputs + local stats ---
    float s[2] = {0.f, 0.f}, q[2] = {0.f, 0.f};
#pragma unroll
    for (int p = 0; p < 4; ++p) {
#pragma unroll
        for (int c = 0; c < 2; ++c) {
            float2 v = unpack2(acc[p][c]);
            int m = mbase + m0 + 2 * p;
            if (m < N)     out[(size_t)m * 32 + 2 * tx + c] = v.x;
            if (m + 1 < N) out[(size_t)(m + 1) * 32 + 2 * tx + c] = v.y;
            float vx = (m < N)     ? v.x : 0.f;
            float vy = (m + 1 < N) ? v.y : 0.f;
            s[c] += vx + vy;
            q[c] += vx * vx + vy * vy;
        }
    }

    __syncthreads();   // done reading Asm region (Red aliases nothing, but keep order)
    Red[my * 32 + 2 * tx + 0]       = s[0];
    Red[my * 32 + 2 * tx + 1]       = s[1];
    Red[512 + my * 32 + 2 * tx + 0] = q[0];
    Red[512 + my * 32 + 2 * tx + 1] = q[1];
    __syncthreads();
    if (tid < 64) {
        int plane = tid >> 5, c = tid & 31;
        float v = 0.f;
#pragma unroll
        for (int i = 0; i < 16; ++i) v += Red[plane * 512 + i * 32 + c];
        atomicAdd(stats + plane * 32 + c, v);
    }
}

// ---------------------------------------------------------------------------
// BN (training-mode stats over all voxels) + ELU, elementwise, float4 vectors.
// ---------------------------------------------------------------------------
__global__ __launch_bounds__(256)
void bnelu_kernel(const float* __restrict__ x, float* __restrict__ y,
                  const float* __restrict__ stats,
                  const float* __restrict__ gamma, const float* __restrict__ beta,
                  int N)
{
    __shared__ float sc[32], sh[32];
    if (threadIdx.x < 32) {
        int c = threadIdx.x;
        float inv  = 1.0f / (float)N;
        float mean = stats[c] * inv;
        float var  = stats[32 + c] * inv - mean * mean;
        float rstd = rsqrtf(var + EPS);
        float sfac = rstd * gamma[c];
        sc[c] = sfac;
        sh[c] = beta[c] - mean * sfac;
    }
    __syncthreads();

    const int total4 = N * 8;   // N*32 / 4
    for (int i = blockIdx.x * blockDim.x + threadIdx.x; i < total4;
         i += gridDim.x * blockDim.x) {
        float4 v = ((const float4*)x)[i];
        int c = (i * 4) & 31;
        float z;
        z = v.x * sc[c + 0] + sh[c + 0]; v.x = (z > 0.f) ? z : expm1f(z);
        z = v.y * sc[c + 1] + sh[c + 1]; v.y = (z > 0.f) ? z : expm1f(z);
        z = v.z * sc[c + 2] + sh[c + 2]; v.z = (z > 0.f) ? z : expm1f(z);
        z = v.w * sc[c + 3] + sh[c + 3]; v.w = (z > 0.f) ? z : expm1f(z);
        ((float4*)y)[i] = v;
    }
}

// ---------------------------------------------------------------------------
extern "C" void kernel_launch(void* const* d_in, const int* in_sizes, int n_in,
                              void* d_out, int out_size)
{
    const float* feats = (const float*)d_in[0];
    const float* W1    = (const float*)d_in[1];
    const float* g1    = (const float*)d_in[2];
    const float* b1    = (const float*)d_in[3];
    const float* W2    = (const float*)d_in[4];
    const float* g2    = (const float*)d_in[5];
    const float* b2    = (const float*)d_in[6];
    const float* W3    = (const float*)d_in[7];
    const float* g3    = (const float*)d_in[8];
    const float* b3    = (const float*)d_in[9];
    const int*   nmap3 = (const int*)d_in[10];
    const int*   nmap2 = (const int*)d_in[11];

    const int N = in_sizes[0] / 32;

    float *bufA, *bufB, *stats;
    cudaGetSymbolAddress((void**)&bufA,  g_bufA);
    cudaGetSymbolAddress((void**)&bufB,  g_bufB);
    cudaGetSymbolAddress((void**)&stats, g_stats);

    cudaMemsetAsync(stats, 0, 3 * 64 * sizeof(float), 0);

    const int blocks = (N + MT - 1) / MT;

    conv_kernel <<<blocks, 256>>>(feats, nmap3, W1, bufA, stats +   0, 27, N);
    bnelu_kernel<<<512,    256>>>(bufA, bufA, stats +   0, g1, b1, N);

    conv_kernel <<<blocks, 256>>>(bufA, nmap2, W2, bufB, stats +  64,  8, N);
    bnelu_kernel<<<512,    256>>>(bufB, bufB, stats +  64, g2, b2, N);

    conv_kernel <<<blocks, 256>>>(bufB, nmap3, W3, bufA, stats + 128, 27, N);
    bnelu_kernel<<<512,    256>>>(bufA, (float*)d_out, stats + 128, g3, b3, N);
}

// round 3
// speedup vs baseline: 1.9307x; 1.9307x over previous
#include <cuda_runtime.h>
#include <math.h>
#include <stdint.h>

// ---------------------------------------------------------------------------
// CompletionNet via warp-level tf32 mma.sync (baseline PTX -> works on sm_103
// without the 'a' target). Split-B (hi+lo tf32) for accuracy.
// conv: gather rows via nmap -> smem (double buffered) -> m16n8k8 tf32 MMA,
// accumulate over kernel offsets in registers. BN stats fused into epilogue.
// ---------------------------------------------------------------------------

#define NMAX 500000
#define EPS  1e-5f
#define PAD  36                      // floats per A row in smem (32 + 4 pad)

__device__ float g_bufA[NMAX * 32];
__device__ float g_bufB[NMAX * 32];
__device__ float g_stats[3 * 64];    // per layer: sum[32], sumsq[32]
__device__ float g_Wp[62 * 2048];    // prepped W: per k: hi frag[1024], lo frag[1024]

typedef unsigned int u32;

__device__ __forceinline__ u32 tf32_rna(float x) {
    u32 y; asm("cvt.rna.tf32.f32 %0, %1;" : "=r"(y) : "f"(x)); return y;
}

#define MMA_TF32(d, a0, a1, a2, a3, b0, b1)                                     \
    asm volatile("mma.sync.aligned.m16n8k8.row.col.f32.tf32.tf32.f32 "          \
                 "{%0,%1,%2,%3}, {%4,%5,%6,%7}, {%8,%9}, {%0,%1,%2,%3};"        \
                 : "+f"(d[0]), "+f"(d[1]), "+f"(d[2]), "+f"(d[3])               \
                 : "r"(a0), "r"(a1), "r"(a2), "r"(a3), "r"(b0), "r"(b1))

// ---------------------------------------------------------------------------
// Weight prep: tf32 hi/lo split, laid out in B-fragment order.
// Fragment index t = kt*256 + nt*64 + lane*2 + p  (p = b0/b1 reg)
//   b_p = W[ci = kt*8 + lane%4 + p*4][co = nt*8 + lane/4]
// ---------------------------------------------------------------------------
__global__ void prep_weights(const float* __restrict__ W, float* __restrict__ dst) {
    int k = blockIdx.x;
    int t = threadIdx.x;                 // 0..1023
    int p = t & 1, lane = (t >> 1) & 31, nt = (t >> 6) & 3, kt = t >> 8;
    int ci = kt * 8 + (lane & 3) + p * 4;
    int co = nt * 8 + (lane >> 2);
    float w  = W[k * 1024 + ci * 32 + co];
    float hi = __uint_as_float(tf32_rna(w));
    float lo = __uint_as_float(tf32_rna(w - hi));
    dst[k * 2048 + t]        = hi;
    dst[k * 2048 + 1024 + t] = lo;
}

// ---------------------------------------------------------------------------
// conv: block = 256 threads (8 warps), tile = 256 voxels x 32 out-channels.
// Warp w owns rows [w*32, w*32+32): 2 m-tiles of 16. K=32 per offset.
// Double-buffered A (256x36 floats) and W (2048 floats) in smem.
// ---------------------------------------------------------------------------
__global__ __launch_bounds__(256, 2)
void conv_mma(const float* __restrict__ in, const int* __restrict__ nmap,
              const float* __restrict__ Wp, float* __restrict__ out,
              float* __restrict__ stats, int kvol, int N)
{
    extern __shared__ float sm[];
    float* As  = sm;                     // [2][256*PAD]
    float* Ws  = sm + 2 * 256 * PAD;     // [2][2048]
    float* Red = Ws + 2 * 2048;          // [8][64]

    const int tid  = threadIdx.x;
    const int wid  = tid >> 5, lane = tid & 31;
    const int gid  = lane >> 2, tg = lane & 3;
    const int mbase = blockIdx.x * 256;
    const int m = mbase + tid;
    const bool mv = (m < N);

    float acc[2][4][4];
#pragma unroll
    for (int mt = 0; mt < 2; ++mt)
#pragma unroll
        for (int nt = 0; nt < 4; ++nt)
#pragma unroll
            for (int j = 0; j < 4; ++j) acc[mt][nt][j] = 0.f;

    // ---- prefetch k=0 (and nmap for k=1) ----
    int idx_cur = mv ? __ldg(nmap + m) : -1;
    int idx_nxt = (mv && kvol > 1) ? __ldg(nmap + (size_t)N + m) : -1;

    float4 ar[8];
    {
        if (idx_cur >= 0) {
            const float4* p = (const float4*)in + (size_t)idx_cur * 8;
#pragma unroll
            for (int q = 0; q < 8; ++q) ar[q] = __ldg(p + q);
        } else {
#pragma unroll
            for (int q = 0; q < 8; ++q) ar[q] = make_float4(0.f, 0.f, 0.f, 0.f);
        }
    }
    float4 wr0 = __ldg((const float4*)Wp + tid);
    float4 wr1 = __ldg((const float4*)Wp + 256 + tid);

    for (int k = 0; k < kvol; ++k) {
        const int buf = k & 1;
        float* Asb = As + buf * (256 * PAD);
        float* Wsb = Ws + buf * 2048;

        // ---- stage current buffers (convert A to tf32 on the way) ----
        {
            float4* arow = (float4*)(Asb + tid * PAD);
#pragma unroll
            for (int q = 0; q < 8; ++q) {
                float4 v = ar[q];
                float4 t;
                t.x = __uint_as_float(tf32_rna(v.x));
                t.y = __uint_as_float(tf32_rna(v.y));
                t.z = __uint_as_float(tf32_rna(v.z));
                t.w = __uint_as_float(tf32_rna(v.w));
                arow[q] = t;
            }
            ((float4*)Wsb)[tid]       = wr0;
            ((float4*)Wsb)[tid + 256] = wr1;
        }

        // ---- prefetch k+1 into registers (flies during the MMAs below) ----
        if (k + 1 < kvol) {
            if (idx_nxt >= 0) {
                const float4* p = (const float4*)in + (size_t)idx_nxt * 8;
#pragma unroll
                for (int q = 0; q < 8; ++q) ar[q] = __ldg(p + q);
            } else {
#pragma unroll
                for (int q = 0; q < 8; ++q) ar[q] = make_float4(0.f, 0.f, 0.f, 0.f);
            }
            const float4* wsrc = (const float4*)(Wp + (size_t)(k + 1) * 2048);
            wr0 = __ldg(wsrc + tid);
            wr1 = __ldg(wsrc + 256 + tid);
        }
        int idx_n2 = (mv && k + 2 < kvol) ? __ldg(nmap + (size_t)(k + 2) * N + m) : -1;
        idx_cur = idx_nxt; idx_nxt = idx_n2;

        __syncthreads();

        // ---- MMA on staged buffer ----
        const float* Aw = Asb + wid * 32 * PAD;
#pragma unroll
        for (int kt = 0; kt < 4; ++kt) {
            u32 bh[4][2], bl[4][2];
#pragma unroll
            for (int nt = 0; nt < 4; ++nt) {
                float2 h = *(const float2*)(Wsb + kt * 256 + nt * 64 + lane * 2);
                float2 l = *(const float2*)(Wsb + 1024 + kt * 256 + nt * 64 + lane * 2);
                bh[nt][0] = __float_as_uint(h.x); bh[nt][1] = __float_as_uint(h.y);
                bl[nt][0] = __float_as_uint(l.x); bl[nt][1] = __float_as_uint(l.y);
            }
#pragma unroll
            for (int mt = 0; mt < 2; ++mt) {
                const float* ap = Aw + (mt * 16 + gid) * PAD + kt * 8 + tg;
                u32 a0 = __float_as_uint(ap[0]);
                u32 a2 = __float_as_uint(ap[4]);
                u32 a1 = __float_as_uint(ap[8 * PAD]);
                u32 a3 = __float_as_uint(ap[8 * PAD + 4]);
#pragma unroll
                for (int nt = 0; nt < 4; ++nt) {
                    MMA_TF32(acc[mt][nt], a0, a1, a2, a3, bh[nt][0], bh[nt][1]);
                    MMA_TF32(acc[mt][nt], a0, a1, a2, a3, bl[nt][0], bl[nt][1]);
                }
            }
        }
        __syncthreads();   // everyone done with this buffer before re-staging
    }

    // ---- epilogue: store + fused BN stats ----
    // acc[mt][nt]: d0,d1 -> (row gid,   cols tg*2, tg*2+1)
    //              d2,d3 -> (row gid+8, cols tg*2, tg*2+1)
    const int rbase = mbase + wid * 32;
#pragma unroll
    for (int mt = 0; mt < 2; ++mt) {
        int r0 = rbase + mt * 16 + gid;
        int r1 = r0 + 8;
#pragma unroll
        for (int nt = 0; nt < 4; ++nt) {
            int c0 = nt * 8 + tg * 2;
            if (r0 < N) *(float2*)(out + (size_t)r0 * 32 + c0) =
                make_float2(acc[mt][nt][0], acc[mt][nt][1]);
            if (r1 < N) *(float2*)(out + (size_t)r1 * 32 + c0) =
                make_float2(acc[mt][nt][2], acc[mt][nt][3]);
        }
    }

    // per-thread channel partials (rows >= N contribute exact zeros)
    float s[4][2], q[4][2];
#pragma unroll
    for (int nt = 0; nt < 4; ++nt)
#pragma unroll
        for (int j = 0; j < 2; ++j) {
            float v0 = acc[0][nt][j],     v1 = acc[0][nt][2 + j];
            float v2 = acc[1][nt][j],     v3 = acc[1][nt][2 + j];
            s[nt][j] = v0 + v1 + v2 + v3;
            q[nt][j] = v0 * v0 + v1 * v1 + v2 * v2 + v3 * v3;
        }
    // reduce across the 8 lanes sharing the same tg (lane % 4)
#pragma unroll
    for (int off = 4; off < 32; off <<= 1)
#pragma unroll
        for (int nt = 0; nt < 4; ++nt)
#pragma unroll
            for (int j = 0; j < 2; ++j) {
                s[nt][j] += __shfl_xor_sync(0xffffffffu, s[nt][j], off);
                q[nt][j] += __shfl_xor_sync(0xffffffffu, q[nt][j], off);
            }
    if (lane < 4) {
#pragma unroll
        for (int nt = 0; nt < 4; ++nt)
#pragma unroll
            for (int j = 0; j < 2; ++j) {
                int c = nt * 8 + tg * 2 + j;
                Red[wid * 64 + c]      = s[nt][j];
                Red[wid * 64 + 32 + c] = q[nt][j];
            }
    }
    __syncthreads();
    if (tid < 64) {
        int plane = tid >> 5, c = tid & 31;
        float v = 0.f;
#pragma unroll
        for (int i = 0; i < 8; ++i) v += Red[i * 64 + plane * 32 + c];
        atomicAdd(stats + plane * 32 + c, v);
    }
}

// ---------------------------------------------------------------------------
// BN (training-mode stats over all voxels) + ELU, elementwise float4.
// ---------------------------------------------------------------------------
__global__ __launch_bounds__(256)
void bnelu_kernel(const float* __restrict__ x, float* __restrict__ y,
                  const float* __restrict__ stats,
                  const float* __restrict__ gamma, const float* __restrict__ beta,
                  int N)
{
    __shared__ float sc[32], sh[32];
    if (threadIdx.x < 32) {
        int c = threadIdx.x;
        float inv  = 1.0f / (float)N;
        float mean = stats[c] * inv;
        float var  = stats[32 + c] * inv - mean * mean;
        float sfac = rsqrtf(var + EPS) * gamma[c];
        sc[c] = sfac;
        sh[c] = beta[c] - mean * sfac;
    }
    __syncthreads();
    const int total4 = N * 8;
    for (int i = blockIdx.x * blockDim.x + threadIdx.x; i < total4;
         i += gridDim.x * blockDim.x) {
        float4 v = ((const float4*)x)[i];
        int c = (i * 4) & 31;
        float z;
        z = v.x * sc[c + 0] + sh[c + 0]; v.x = (z > 0.f) ? z : expm1f(z);
        z = v.y * sc[c + 1] + sh[c + 1]; v.y = (z > 0.f) ? z : expm1f(z);
        z = v.z * sc[c + 2] + sh[c + 2]; v.z = (z > 0.f) ? z : expm1f(z);
        z = v.w * sc[c + 3] + sh[c + 3]; v.w = (z > 0.f) ? z : expm1f(z);
        ((float4*)y)[i] = v;
    }
}

// ---------------------------------------------------------------------------
#define SMEM_BYTES ((2 * 256 * PAD + 2 * 2048 + 8 * 64) * 4)

extern "C" void kernel_launch(void* const* d_in, const int* in_sizes, int n_in,
                              void* d_out, int out_size)
{
    const float* feats = (const float*)d_in[0];
    const float* W1    = (const float*)d_in[1];
    const float* g1    = (const float*)d_in[2];
    const float* b1    = (const float*)d_in[3];
    const float* W2    = (const float*)d_in[4];
    const float* g2    = (const float*)d_in[5];
    const float* b2    = (const float*)d_in[6];
    const float* W3    = (const float*)d_in[7];
    const float* g3    = (const float*)d_in[8];
    const float* b3    = (const float*)d_in[9];
    const int*   nmap3 = (const int*)d_in[10];
    const int*   nmap2 = (const int*)d_in[11];

    const int N = in_sizes[0] / 32;
    const int ntiles = (N + 255) / 256;

    float *bufA, *bufB, *stats, *Wp;
    cudaGetSymbolAddress((void**)&bufA,  g_bufA);
    cudaGetSymbolAddress((void**)&bufB,  g_bufB);
    cudaGetSymbolAddress((void**)&stats, g_stats);
    cudaGetSymbolAddress((void**)&Wp,    g_Wp);

    cudaFuncSetAttribute(conv_mma, cudaFuncAttributeMaxDynamicSharedMemorySize, SMEM_BYTES);

    cudaMemsetAsync(stats, 0, 3 * 64 * sizeof(float), 0);
    prep_weights<<<27, 1024>>>(W1, Wp + 0 * 2048);
    prep_weights<<< 8, 1024>>>(W2, Wp + 27 * 2048);
    prep_weights<<<27, 1024>>>(W3, Wp + 35 * 2048);

    conv_mma<<<ntiles, 256, SMEM_BYTES>>>(feats, nmap3, Wp + 0 * 2048, bufA, stats + 0, 27, N);
    bnelu_kernel<<<2048, 256>>>(bufA, bufA, stats + 0, g1, b1, N);

    conv_mma<<<ntiles, 256, SMEM_BYTES>>>(bufA, nmap2, Wp + 27 * 2048, bufB, stats + 64, 8, N);
    bnelu_kernel<<<2048, 256>>>(bufB, bufB, stats + 64, g2, b2, N);

    conv_mma<<<ntiles, 256, SMEM_BYTES>>>(bufB, nmap3, Wp + 35 * 2048, bufA, stats + 128, 27, N);
    bnelu_kernel<<<2048, 256>>>(bufA, (float*)d_out, stats + 128, g3, b3, N);
}

// round 4
// speedup vs baseline: 2.1002x; 1.0878x over previous
#include <cuda_runtime.h>
#include <math.h>
#include <stdint.h>

// ---------------------------------------------------------------------------
// CompletionNet via warp-level tf32 mma.sync, register-direct fragment gather.
// Physical ci permutation (ci = tg*8 + kt*2 + h) makes each lane's A-fragment
// bytes contiguous -> gather = 8x LDG.128 per warp per offset, no smem staging.
// W prepacked per fragment as {b0hi,b1hi,b0lo,b1lo} (split-B for accuracy).
// BN stats fused into conv epilogue; BN+ELU as separate elementwise pass.
// ---------------------------------------------------------------------------

#define NMAX 500000
#define EPS  1e-5f

__device__ float g_bufA[NMAX * 32];
__device__ float g_bufB[NMAX * 32];
__device__ float g_stats[3 * 64];    // per layer: sum[32], sumsq[32]
__device__ float g_Wp[62 * 2048];    // per k: 512 float4 fragments

typedef unsigned int u32;

__device__ __forceinline__ u32 tf32_rna(float x) {
    u32 y; asm("cvt.rna.tf32.f32 %0, %1;" : "=r"(y) : "f"(x)); return y;
}

#define MMA_TF32(d, a0, a1, a2, a3, b0, b1)                                     \
    asm volatile("mma.sync.aligned.m16n8k8.row.col.f32.tf32.tf32.f32 "          \
                 "{%0,%1,%2,%3}, {%4,%5,%6,%7}, {%8,%9}, {%0,%1,%2,%3};"        \
                 : "+f"(d[0]), "+f"(d[1]), "+f"(d[2]), "+f"(d[3])               \
                 : "r"(a0), "r"(a1), "r"(a2), "r"(a3), "r"(b0), "r"(b1))

// ---------------------------------------------------------------------------
// Weight prep. Thread t = kt*128 + nt*32 + lane writes one float4 fragment:
//   {hi(p=0), hi(p=1), lo(p=0), lo(p=1)}
// B fragment row c = (lane&3) + 4p maps to PHYSICAL ci = (lane&3)*8 + kt*2 + p
// (the same permutation the A gather uses); col co = nt*8 + lane/4.
// ---------------------------------------------------------------------------
__global__ void prep_weights(const float* __restrict__ W, float* __restrict__ dst) {
    int k = blockIdx.x;
    int t = threadIdx.x;                 // 0..511
    int lane = t & 31, nt = (t >> 5) & 3, kt = t >> 7;
    int co  = nt * 8 + (lane >> 2);
    int tgb = lane & 3;
    int ci0 = tgb * 8 + kt * 2 + 0;
    int ci1 = tgb * 8 + kt * 2 + 1;
    float w0 = W[k * 1024 + ci0 * 32 + co];
    float w1 = W[k * 1024 + ci1 * 32 + co];
    float h0 = __uint_as_float(tf32_rna(w0));
    float h1 = __uint_as_float(tf32_rna(w1));
    float l0 = __uint_as_float(tf32_rna(w0 - h0));
    float l1 = __uint_as_float(tf32_rna(w1 - h1));
    ((float4*)dst)[k * 512 + t] = make_float4(h0, h1, l0, l1);
}

// ---------------------------------------------------------------------------
// conv: block = 256 threads (8 warps), tile = 256 voxels x 32 out-channels.
// Warp owns 32 rows (2 m-tiles of 16). Per k: 1 idx load + 4 shfl +
// 8 gather LDG.128 + 16 W LDG.128 (L1-hot) + 64 MMAs. No smem in main loop.
// ---------------------------------------------------------------------------
__global__ __launch_bounds__(256, 2)
void conv_mma(const float* __restrict__ in, const int* __restrict__ nmap,
              const float* __restrict__ Wp, float* __restrict__ out,
              float* __restrict__ stats, int kvol, int N)
{
    __shared__ float Red[8 * 64];

    const int tid  = threadIdx.x;
    const int wid  = tid >> 5, lane = tid & 31;
    const int gid  = lane >> 2, tg = lane & 3;
    const int mbase = blockIdx.x * 256;
    const int mrow  = mbase + wid * 32 + lane;   // lane's idx-load row
    const bool mv   = (mrow < N);

    float acc[2][4][4];
#pragma unroll
    for (int mt = 0; mt < 2; ++mt)
#pragma unroll
        for (int nt = 0; nt < 4; ++nt)
#pragma unroll
            for (int j = 0; j < 4; ++j) acc[mt][nt][j] = 0.f;

    int idxk = mv ? __ldg(nmap + mrow) : -1;

    for (int k = 0; k < kvol; ++k) {
        // row indices for this k (idxk currently holds offset k)
        const int iA = __shfl_sync(0xffffffffu, idxk, gid);        // mt0 rows 0-7
        const int iB = __shfl_sync(0xffffffffu, idxk, 8 + gid);    // mt0 rows 8-15
        const int iC = __shfl_sync(0xffffffffu, idxk, 16 + gid);   // mt1 rows 16-23
        const int iD = __shfl_sync(0xffffffffu, idxk, 24 + gid);   // mt1 rows 24-31
        // prefetch next offset's indices
        idxk = (k + 1 < kvol && mv) ? __ldg(nmap + (size_t)(k + 1) * N + mrow) : -1;

        // gather: lane reads floats [tg*8, tg*8+8) of each needed row
        float4 gA0 = make_float4(0,0,0,0), gA1 = gA0, gB0 = gA0, gB1 = gA0;
        float4 gC0 = gA0, gC1 = gA0, gD0 = gA0, gD1 = gA0;
        if (iA >= 0) { const float4* p = (const float4*)(in + (size_t)iA * 32) + tg * 2; gA0 = __ldg(p); gA1 = __ldg(p + 1); }
        if (iB >= 0) { const float4* p = (const float4*)(in + (size_t)iB * 32) + tg * 2; gB0 = __ldg(p); gB1 = __ldg(p + 1); }
        if (iC >= 0) { const float4* p = (const float4*)(in + (size_t)iC * 32) + tg * 2; gC0 = __ldg(p); gC1 = __ldg(p + 1); }
        if (iD >= 0) { const float4* p = (const float4*)(in + (size_t)iD * 32) + tg * 2; gD0 = __ldg(p); gD1 = __ldg(p + 1); }

        // convert to tf32 fragments, per kt:
        //  a0[kt] from g?0/g?1 {.x,.z}, a2[kt] from {.y,.w}   (rows r)
        //  a1,a3 same from the +8 row group
        u32 A0[4] = { tf32_rna(gA0.x), tf32_rna(gA0.z), tf32_rna(gA1.x), tf32_rna(gA1.z) };
        u32 A2[4] = { tf32_rna(gA0.y), tf32_rna(gA0.w), tf32_rna(gA1.y), tf32_rna(gA1.w) };
        u32 A1[4] = { tf32_rna(gB0.x), tf32_rna(gB0.z), tf32_rna(gB1.x), tf32_rna(gB1.z) };
        u32 A3[4] = { tf32_rna(gB0.y), tf32_rna(gB0.w), tf32_rna(gB1.y), tf32_rna(gB1.w) };
        u32 C0[4] = { tf32_rna(gC0.x), tf32_rna(gC0.z), tf32_rna(gC1.x), tf32_rna(gC1.z) };
        u32 C2[4] = { tf32_rna(gC0.y), tf32_rna(gC0.w), tf32_rna(gC1.y), tf32_rna(gC1.w) };
        u32 C1[4] = { tf32_rna(gD0.x), tf32_rna(gD0.z), tf32_rna(gD1.x), tf32_rna(gD1.z) };
        u32 C3[4] = { tf32_rna(gD0.y), tf32_rna(gD0.w), tf32_rna(gD1.y), tf32_rna(gD1.w) };

        const float4* wb = (const float4*)Wp + (size_t)k * 512 + lane;
#pragma unroll
        for (int kt = 0; kt < 4; ++kt) {
#pragma unroll
            for (int nt = 0; nt < 4; ++nt) {
                float4 w = __ldg(wb + kt * 128 + nt * 32);
                u32 bh0 = __float_as_uint(w.x), bh1 = __float_as_uint(w.y);
                u32 bl0 = __float_as_uint(w.z), bl1 = __float_as_uint(w.w);
                MMA_TF32(acc[0][nt], A0[kt], A1[kt], A2[kt], A3[kt], bh0, bh1);
                MMA_TF32(acc[0][nt], A0[kt], A1[kt], A2[kt], A3[kt], bl0, bl1);
                MMA_TF32(acc[1][nt], C0[kt], C1[kt], C2[kt], C3[kt], bh0, bh1);
                MMA_TF32(acc[1][nt], C0[kt], C1[kt], C2[kt], C3[kt], bl0, bl1);
            }
        }
    }

    // ---- epilogue: store + fused BN stats ----
    const int rbase = mbase + wid * 32;
#pragma unroll
    for (int mt = 0; mt < 2; ++mt) {
        int r0 = rbase + mt * 16 + gid;
        int r1 = r0 + 8;
#pragma unroll
        for (int nt = 0; nt < 4; ++nt) {
            int c0 = nt * 8 + tg * 2;
            if (r0 < N) *(float2*)(out + (size_t)r0 * 32 + c0) =
                make_float2(acc[mt][nt][0], acc[mt][nt][1]);
            if (r1 < N) *(float2*)(out + (size_t)r1 * 32 + c0) =
                make_float2(acc[mt][nt][2], acc[mt][nt][3]);
        }
    }

    float s[4][2], q[4][2];
#pragma unroll
    for (int nt = 0; nt < 4; ++nt)
#pragma unroll
        for (int j = 0; j < 2; ++j) {
            float v0 = acc[0][nt][j],     v1 = acc[0][nt][2 + j];
            float v2 = acc[1][nt][j],     v3 = acc[1][nt][2 + j];
            s[nt][j] = v0 + v1 + v2 + v3;
            q[nt][j] = v0 * v0 + v1 * v1 + v2 * v2 + v3 * v3;
        }
#pragma unroll
    for (int off = 4; off < 32; off <<= 1)
#pragma unroll
        for (int nt = 0; nt < 4; ++nt)
#pragma unroll
            for (int j = 0; j < 2; ++j) {
                s[nt][j] += __shfl_xor_sync(0xffffffffu, s[nt][j], off);
                q[nt][j] += __shfl_xor_sync(0xffffffffu, q[nt][j], off);
            }
    if (lane < 4) {
#pragma unroll
        for (int nt = 0; nt < 4; ++nt)
#pragma unroll
            for (int j = 0; j < 2; ++j) {
                int c = nt * 8 + tg * 2 + j;
                Red[wid * 64 + c]      = s[nt][j];
                Red[wid * 64 + 32 + c] = q[nt][j];
            }
    }
    __syncthreads();
    if (tid < 64) {
        int plane = tid >> 5, c = tid & 31;
        float v = 0.f;
#pragma unroll
        for (int i = 0; i < 8; ++i) v += Red[i * 64 + plane * 32 + c];
        atomicAdd(stats + plane * 32 + c, v);
    }
}

// ---------------------------------------------------------------------------
// BN (training-mode stats over all voxels) + ELU, elementwise float4.
// ---------------------------------------------------------------------------
__global__ __launch_bounds__(256)
void bnelu_kernel(const float* __restrict__ x, float* __restrict__ y,
                  const float* __restrict__ stats,
                  const float* __restrict__ gamma, const float* __restrict__ beta,
                  int N)
{
    __shared__ float sc[32], sh[32];
    if (threadIdx.x < 32) {
        int c = threadIdx.x;
        float inv  = 1.0f / (float)N;
        float mean = stats[c] * inv;
        float var  = stats[32 + c] * inv - mean * mean;
        float sfac = rsqrtf(var + EPS) * gamma[c];
        sc[c] = sfac;
        sh[c] = beta[c] - mean * sfac;
    }
    __syncthreads();
    const int total4 = N * 8;
    for (int i = blockIdx.x * blockDim.x + threadIdx.x; i < total4;
         i += gridDim.x * blockDim.x) {
        float4 v = ((const float4*)x)[i];
        int c = (i * 4) & 31;
        float z;
        z = v.x * sc[c + 0] + sh[c + 0]; v.x = (z > 0.f) ? z : expm1f(z);
        z = v.y * sc[c + 1] + sh[c + 1]; v.y = (z > 0.f) ? z : expm1f(z);
        z = v.z * sc[c + 2] + sh[c + 2]; v.z = (z > 0.f) ? z : expm1f(z);
        z = v.w * sc[c + 3] + sh[c + 3]; v.w = (z > 0.f) ? z : expm1f(z);
        ((float4*)y)[i] = v;
    }
}

// ---------------------------------------------------------------------------
extern "C" void kernel_launch(void* const* d_in, const int* in_sizes, int n_in,
                              void* d_out, int out_size)
{
    const float* feats = (const float*)d_in[0];
    const float* W1    = (const float*)d_in[1];
    const float* g1    = (const float*)d_in[2];
    const float* b1    = (const float*)d_in[3];
    const float* W2    = (const float*)d_in[4];
    const float* g2    = (const float*)d_in[5];
    const float* b2    = (const float*)d_in[6];
    const float* W3    = (const float*)d_in[7];
    const float* g3    = (const float*)d_in[8];
    const float* b3    = (const float*)d_in[9];
    const int*   nmap3 = (const int*)d_in[10];
    const int*   nmap2 = (const int*)d_in[11];

    const int N = in_sizes[0] / 32;
    const int ntiles = (N + 255) / 256;

    float *bufA, *bufB, *stats, *Wp;
    cudaGetSymbolAddress((void**)&bufA,  g_bufA);
    cudaGetSymbolAddress((void**)&bufB,  g_bufB);
    cudaGetSymbolAddress((void**)&stats, g_stats);
    cudaGetSymbolAddress((void**)&Wp,    g_Wp);

    cudaMemsetAsync(stats, 0, 3 * 64 * sizeof(float), 0);
    prep_weights<<<27, 512>>>(W1, Wp + 0 * 2048);
    prep_weights<<< 8, 512>>>(W2, Wp + 27 * 2048);
    prep_weights<<<27, 512>>>(W3, Wp + 35 * 2048);

    conv_mma<<<ntiles, 256>>>(feats, nmap3, Wp + 0 * 2048, bufA, stats + 0, 27, N);
    bnelu_kernel<<<2048, 256>>>(bufA, bufA, stats + 0, g1, b1, N);

    conv_mma<<<ntiles, 256>>>(bufA, nmap2, Wp + 27 * 2048, bufB, stats + 64, 8, N);
    bnelu_kernel<<<2048, 256>>>(bufB, bufB, stats + 64, g2, b2, N);

    conv_mma<<<ntiles, 256>>>(bufB, nmap3, Wp + 35 * 2048, bufA, stats + 128, 27, N);
    bnelu_kernel<<<2048, 256>>>(bufA, (float*)d_out, stats + 128, g3, b3, N);
}

// round 5
// speedup vs baseline: 2.7519x; 1.3103x over previous
#include <cuda_runtime.h>
#include <math.h>
#include <stdint.h>

// ---------------------------------------------------------------------------
// CompletionNet via warp-level tf32 mma.sync, register-direct fragment gather.
// All activations are pre-rounded to tf32 by their producer (convert pass for
// feats, fused into bnelu for inter-layer tensors), so the conv hot loop has
// zero cvt instructions. W rounded to tf32 at prep (single MMA per fragment).
// Physical ci permutation (ci = tg*8 + kt*2 + h) makes each lane's A-fragment
// bytes contiguous -> gather = 8x LDG.128 per warp per offset, no smem staging.
// BN stats fused into conv epilogue.
// ---------------------------------------------------------------------------

#define NMAX 500000
#define EPS  1e-5f

__device__ float g_bufA[NMAX * 32];
__device__ float g_bufB[NMAX * 32];
__device__ float g_bufC[NMAX * 32];
__device__ float g_stats[3 * 64];    // per layer: sum[32], sumsq[32]
__device__ float g_Wp[62 * 1024];    // per k: 256 float4 fragment pairs

typedef unsigned int u32;

__device__ __forceinline__ u32 tf32_rna(float x) {
    u32 y; asm("cvt.rna.tf32.f32 %0, %1;" : "=r"(y) : "f"(x)); return y;
}

#define MMA_TF32(d, a0, a1, a2, a3, b0, b1)                                     \
    asm volatile("mma.sync.aligned.m16n8k8.row.col.f32.tf32.tf32.f32 "          \
                 "{%0,%1,%2,%3}, {%4,%5,%6,%7}, {%8,%9}, {%0,%1,%2,%3};"        \
                 : "+f"(d[0]), "+f"(d[1]), "+f"(d[2]), "+f"(d[3])               \
                 : "r"(a0), "r"(a1), "r"(a2), "r"(a3), "r"(b0), "r"(b1))

// ---------------------------------------------------------------------------
// Weight prep (tf32 rounded, fragment-pair packed).
// Thread t = kt*64 + ntp*32 + lane writes float4:
//   { b(kt, 2ntp).p0, b(kt, 2ntp).p1, b(kt, 2ntp+1).p0, b(kt, 2ntp+1).p1 }
// B frag row c=(lane&3)+4p -> PHYSICAL ci=(lane&3)*8 + kt*2 + p ; co=nt*8+lane/4.
// ---------------------------------------------------------------------------
__global__ void prep_weights(const float* __restrict__ W, float* __restrict__ dst) {
    int k = blockIdx.x;
    int t = threadIdx.x;                 // 0..255
    int lane = t & 31, ntp = (t >> 5) & 1, kt = t >> 6;
    int r   = lane >> 2;
    int ci0 = (lane & 3) * 8 + kt * 2 + 0;
    int ci1 = (lane & 3) * 8 + kt * 2 + 1;
    int co0 = (2 * ntp) * 8 + r;
    int co1 = (2 * ntp + 1) * 8 + r;
    float4 w4;
    w4.x = __uint_as_float(tf32_rna(W[k * 1024 + ci0 * 32 + co0]));
    w4.y = __uint_as_float(tf32_rna(W[k * 1024 + ci1 * 32 + co0]));
    w4.z = __uint_as_float(tf32_rna(W[k * 1024 + ci0 * 32 + co1]));
    w4.w = __uint_as_float(tf32_rna(W[k * 1024 + ci1 * 32 + co1]));
    ((float4*)dst)[k * 256 + t] = w4;
}

// ---------------------------------------------------------------------------
// Elementwise tf32 rounding pass (for the first layer's input).
// ---------------------------------------------------------------------------
__global__ __launch_bounds__(256)
void cvt_tf32_kernel(const float* __restrict__ x, float* __restrict__ y, int total4)
{
    for (int i = blockIdx.x * blockDim.x + threadIdx.x; i < total4;
         i += gridDim.x * blockDim.x) {
        float4 v = ((const float4*)x)[i];
        v.x = __uint_as_float(tf32_rna(v.x));
        v.y = __uint_as_float(tf32_rna(v.y));
        v.z = __uint_as_float(tf32_rna(v.z));
        v.w = __uint_as_float(tf32_rna(v.w));
        ((float4*)y)[i] = v;
    }
}

// ---------------------------------------------------------------------------
// conv: block = 256 threads (8 warps), tile = 256 voxels x 32 out-channels.
// Per k per thread: 1 nmap LDG + 4 shfl + 8 gather LDG.128 + 8 W LDG.128
// (L1-hot) + 16 MMAs. Inputs already tf32-rounded.
// ---------------------------------------------------------------------------
__global__ __launch_bounds__(256, 2)
void conv_mma(const float* __restrict__ in, const int* __restrict__ nmap,
              const float* __restrict__ Wp, float* __restrict__ out,
              float* __restrict__ stats, int kvol, int N)
{
    __shared__ float Red[8 * 64];

    const int tid  = threadIdx.x;
    const int wid  = tid >> 5, lane = tid & 31;
    const int gid  = lane >> 2, tg = lane & 3;
    const int mbase = blockIdx.x * 256;
    const int mrow  = mbase + wid * 32 + lane;
    const bool mv   = (mrow < N);

    float acc[2][4][4];
#pragma unroll
    for (int mt = 0; mt < 2; ++mt)
#pragma unroll
        for (int nt = 0; nt < 4; ++nt)
#pragma unroll
            for (int j = 0; j < 4; ++j) acc[mt][nt][j] = 0.f;

    int idxk = mv ? __ldg(nmap + mrow) : -1;

    for (int k = 0; k < kvol; ++k) {
        const int iA = __shfl_sync(0xffffffffu, idxk, gid);
        const int iB = __shfl_sync(0xffffffffu, idxk, 8 + gid);
        const int iC = __shfl_sync(0xffffffffu, idxk, 16 + gid);
        const int iD = __shfl_sync(0xffffffffu, idxk, 24 + gid);
        idxk = (k + 1 < kvol && mv) ? __ldg(nmap + (size_t)(k + 1) * N + mrow) : -1;

        float4 gA0 = make_float4(0,0,0,0), gA1 = gA0, gB0 = gA0, gB1 = gA0;
        float4 gC0 = gA0, gC1 = gA0, gD0 = gA0, gD1 = gA0;
        if (iA >= 0) { const float4* p = (const float4*)(in + (size_t)iA * 32) + tg * 2; gA0 = __ldg(p); gA1 = __ldg(p + 1); }
        if (iB >= 0) { const float4* p = (const float4*)(in + (size_t)iB * 32) + tg * 2; gB0 = __ldg(p); gB1 = __ldg(p + 1); }
        if (iC >= 0) { const float4* p = (const float4*)(in + (size_t)iC * 32) + tg * 2; gC0 = __ldg(p); gC1 = __ldg(p + 1); }
        if (iD >= 0) { const float4* p = (const float4*)(in + (size_t)iD * 32) + tg * 2; gD0 = __ldg(p); gD1 = __ldg(p + 1); }

        // fragments straight from gathered bits (already tf32-rounded values)
        u32 A0[4] = { __float_as_uint(gA0.x), __float_as_uint(gA0.z), __float_as_uint(gA1.x), __float_as_uint(gA1.z) };
        u32 A2[4] = { __float_as_uint(gA0.y), __float_as_uint(gA0.w), __float_as_uint(gA1.y), __float_as_uint(gA1.w) };
        u32 A1[4] = { __float_as_uint(gB0.x), __float_as_uint(gB0.z), __float_as_uint(gB1.x), __float_as_uint(gB1.z) };
        u32 A3[4] = { __float_as_uint(gB0.y), __float_as_uint(gB0.w), __float_as_uint(gB1.y), __float_as_uint(gB1.w) };
        u32 C0[4] = { __float_as_uint(gC0.x), __float_as_uint(gC0.z), __float_as_uint(gC1.x), __float_as_uint(gC1.z) };
        u32 C2[4] = { __float_as_uint(gC0.y), __float_as_uint(gC0.w), __float_as_uint(gC1.y), __float_as_uint(gC1.w) };
        u32 C1[4] = { __float_as_uint(gD0.x), __float_as_uint(gD0.z), __float_as_uint(gD1.x), __float_as_uint(gD1.z) };
        u32 C3[4] = { __float_as_uint(gD0.y), __float_as_uint(gD0.w), __float_as_uint(gD1.y), __float_as_uint(gD1.w) };

        const float4* wb = (const float4*)Wp + (size_t)k * 256 + lane;
#pragma unroll
        for (int kt = 0; kt < 4; ++kt) {
#pragma unroll
            for (int ntp = 0; ntp < 2; ++ntp) {
                float4 w = __ldg(wb + kt * 64 + ntp * 32);
                u32 b00 = __float_as_uint(w.x), b01 = __float_as_uint(w.y);
                u32 b10 = __float_as_uint(w.z), b11 = __float_as_uint(w.w);
                MMA_TF32(acc[0][2 * ntp + 0], A0[kt], A1[kt], A2[kt], A3[kt], b00, b01);
                MMA_TF32(acc[0][2 * ntp + 1], A0[kt], A1[kt], A2[kt], A3[kt], b10, b11);
                MMA_TF32(acc[1][2 * ntp + 0], C0[kt], C1[kt], C2[kt], C3[kt], b00, b01);
                MMA_TF32(acc[1][2 * ntp + 1], C0[kt], C1[kt], C2[kt], C3[kt], b10, b11);
            }
        }
    }

    // ---- epilogue: store + fused BN stats ----
    const int rbase = mbase + wid * 32;
#pragma unroll
    for (int mt = 0; mt < 2; ++mt) {
        int r0 = rbase + mt * 16 + gid;
        int r1 = r0 + 8;
#pragma unroll
        for (int nt = 0; nt < 4; ++nt) {
            int c0 = nt * 8 + tg * 2;
            if (r0 < N) *(float2*)(out + (size_t)r0 * 32 + c0) =
                make_float2(acc[mt][nt][0], acc[mt][nt][1]);
            if (r1 < N) *(float2*)(out + (size_t)r1 * 32 + c0) =
                make_float2(acc[mt][nt][2], acc[mt][nt][3]);
        }
    }

    float s[4][2], q[4][2];
#pragma unroll
    for (int nt = 0; nt < 4; ++nt)
#pragma unroll
        for (int j = 0; j < 2; ++j) {
            float v0 = acc[0][nt][j],     v1 = acc[0][nt][2 + j];
            float v2 = acc[1][nt][j],     v3 = acc[1][nt][2 + j];
            s[nt][j] = v0 + v1 + v2 + v3;
            q[nt][j] = v0 * v0 + v1 * v1 + v2 * v2 + v3 * v3;
        }
#pragma unroll
    for (int off = 4; off < 32; off <<= 1)
#pragma unroll
        for (int nt = 0; nt < 4; ++nt)
#pragma unroll
            for (int j = 0; j < 2; ++j) {
                s[nt][j] += __shfl_xor_sync(0xffffffffu, s[nt][j], off);
                q[nt][j] += __shfl_xor_sync(0xffffffffu, q[nt][j], off);
            }
    if (lane < 4) {
#pragma unroll
        for (int nt = 0; nt < 4; ++nt)
#pragma unroll
            for (int j = 0; j < 2; ++j) {
                int c = nt * 8 + tg * 2 + j;
                Red[wid * 64 + c]      = s[nt][j];
                Red[wid * 64 + 32 + c] = q[nt][j];
            }
    }
    __syncthreads();
    if (tid < 64) {
        int plane = tid >> 5, c = tid & 31;
        float v = 0.f;
#pragma unroll
        for (int i = 0; i < 8; ++i) v += Red[i * 64 + plane * 32 + c];
        atomicAdd(stats + plane * 32 + c, v);
    }
}

// ---------------------------------------------------------------------------
// BN + ELU. If round_tf32 != 0, output is rounded to tf32 (consumed by the
// next conv); the final layer keeps full fp32.
// ---------------------------------------------------------------------------
__global__ __launch_bounds__(256)
void bnelu_kernel(const float* __restrict__ x, float* __restrict__ y,
                  const float* __restrict__ stats,
                  const float* __restrict__ gamma, const float* __restrict__ beta,
                  int N, int round_tf32)
{
    __shared__ float sc[32], sh[32];
    if (threadIdx.x < 32) {
        int c = threadIdx.x;
        float inv  = 1.0f / (float)N;
        float mean = stats[c] * inv;
        float var  = stats[32 + c] * inv - mean * mean;
        float sfac = rsqrtf(var + EPS) * gamma[c];
        sc[c] = sfac;
        sh[c] = beta[c] - mean * sfac;
    }
    __syncthreads();
    const int total4 = N * 8;
    for (int i = blockIdx.x * blockDim.x + threadIdx.x; i < total4;
         i += gridDim.x * blockDim.x) {
        float4 v = ((const float4*)x)[i];
        int c = (i * 4) & 31;
        float z;
        z = v.x * sc[c + 0] + sh[c + 0]; v.x = (z > 0.f) ? z : expm1f(z);
        z = v.y * sc[c + 1] + sh[c + 1]; v.y = (z > 0.f) ? z : expm1f(z);
        z = v.z * sc[c + 2] + sh[c + 2]; v.z = (z > 0.f) ? z : expm1f(z);
        z = v.w * sc[c + 3] + sh[c + 3]; v.w = (z > 0.f) ? z : expm1f(z);
        if (round_tf32) {
            v.x = __uint_as_float(tf32_rna(v.x));
            v.y = __uint_as_float(tf32_rna(v.y));
            v.z = __uint_as_float(tf32_rna(v.z));
            v.w = __uint_as_float(tf32_rna(v.w));
        }
        ((float4*)y)[i] = v;
    }
}

// ---------------------------------------------------------------------------
extern "C" void kernel_launch(void* const* d_in, const int* in_sizes, int n_in,
                              void* d_out, int out_size)
{
    const float* feats = (const float*)d_in[0];
    const float* W1    = (const float*)d_in[1];
    const float* g1    = (const float*)d_in[2];
    const float* b1    = (const float*)d_in[3];
    const float* W2    = (const float*)d_in[4];
    const float* g2    = (const float*)d_in[5];
    const float* b2    = (const float*)d_in[6];
    const float* W3    = (const float*)d_in[7];
    const float* g3    = (const float*)d_in[8];
    const float* b3    = (const float*)d_in[9];
    const int*   nmap3 = (const int*)d_in[10];
    const int*   nmap2 = (const int*)d_in[11];

    const int N = in_sizes[0] / 32;
    const int ntiles = (N + 255) / 256;

    float *bufA, *bufB, *bufC, *stats, *Wp;
    cudaGetSymbolAddress((void**)&bufA,  g_bufA);
    cudaGetSymbolAddress((void**)&bufB,  g_bufB);
    cudaGetSymbolAddress((void**)&bufC,  g_bufC);
    cudaGetSymbolAddress((void**)&stats, g_stats);
    cudaGetSymbolAddress((void**)&Wp,    g_Wp);

    cudaMemsetAsync(stats, 0, 3 * 64 * sizeof(float), 0);
    prep_weights<<<27, 256>>>(W1, Wp + 0 * 1024);
    prep_weights<<< 8, 256>>>(W2, Wp + 27 * 1024);
    prep_weights<<<27, 256>>>(W3, Wp + 35 * 1024);
    cvt_tf32_kernel<<<1024, 256>>>(feats, bufC, N * 8);

    conv_mma<<<ntiles, 256>>>(bufC, nmap3, Wp + 0 * 1024, bufA, stats + 0, 27, N);
    bnelu_kernel<<<2048, 256>>>(bufA, bufA, stats + 0, g1, b1, N, 1);

    conv_mma<<<ntiles, 256>>>(bufA, nmap2, Wp + 27 * 1024, bufB, stats + 64, 8, N);
    bnelu_kernel<<<2048, 256>>>(bufB, bufB, stats + 64, g2, b2, N, 1);

    conv_mma<<<ntiles, 256>>>(bufB, nmap3, Wp + 35 * 1024, bufA, stats + 128, 27, N);
    bnelu_kernel<<<2048, 256>>>(bufA, (float*)d_out, stats + 128, g3, b3, N, 0);
}

// round 6
// speedup vs baseline: 3.3311x; 1.2105x over previous
#include <cuda_runtime.h>
#include <math.h>
#include <stdint.h>

// ---------------------------------------------------------------------------
// CompletionNet via warp-level tf32 mma.sync, register-direct fragment gather,
// one-offset-ahead software pipelining.
// - Activations pre-rounded to tf32 by producer (cvt pass / fused in bnelu),
//   so the conv hot loop has zero cvt instructions.
// - Physical ci permutation (ci = tg*8 + kt*2 + h) makes each lane's
//   A-fragment bytes contiguous: gather = 4x LDG.128 per warp per offset.
// - Warp tile M=16 (block tile 128 voxels) to fit prefetch regs at 3 blocks/SM.
// - BN stats fused into conv epilogue.
// ---------------------------------------------------------------------------

#define NMAX 500000
#define EPS  1e-5f

__device__ float g_bufA[NMAX * 32];
__device__ float g_bufB[NMAX * 32];
__device__ float g_bufC[NMAX * 32];
__device__ float g_stats[3 * 64];    // per layer: sum[32], sumsq[32]
__device__ float g_Wp[62 * 1024];    // per k: 256 float4 fragment pairs

typedef unsigned int u32;

__device__ __forceinline__ u32 tf32_rna(float x) {
    u32 y; asm("cvt.rna.tf32.f32 %0, %1;" : "=r"(y) : "f"(x)); return y;
}

#define MMA_TF32(d, a0, a1, a2, a3, b0, b1)                                     \
    asm volatile("mma.sync.aligned.m16n8k8.row.col.f32.tf32.tf32.f32 "          \
                 "{%0,%1,%2,%3}, {%4,%5,%6,%7}, {%8,%9}, {%0,%1,%2,%3};"        \
                 : "+f"(d[0]), "+f"(d[1]), "+f"(d[2]), "+f"(d[3])               \
                 : "r"(a0), "r"(a1), "r"(a2), "r"(a3), "r"(b0), "r"(b1))

// ---------------------------------------------------------------------------
// Weight prep (tf32 rounded, fragment-pair packed).
// Thread t = kt*64 + ntp*32 + lane writes float4:
//   { b(kt,2ntp).p0, b(kt,2ntp).p1, b(kt,2ntp+1).p0, b(kt,2ntp+1).p1 }
// B frag row c=(lane&3)+4p -> PHYSICAL ci=(lane&3)*8 + kt*2 + p ; co=nt*8+lane/4.
// ---------------------------------------------------------------------------
__global__ void prep_weights(const float* __restrict__ W, float* __restrict__ dst) {
    int k = blockIdx.x;
    int t = threadIdx.x;                 // 0..255
    int lane = t & 31, ntp = (t >> 5) & 1, kt = t >> 6;
    int r   = lane >> 2;
    int ci0 = (lane & 3) * 8 + kt * 2 + 0;
    int ci1 = (lane & 3) * 8 + kt * 2 + 1;
    int co0 = (2 * ntp) * 8 + r;
    int co1 = (2 * ntp + 1) * 8 + r;
    float4 w4;
    w4.x = __uint_as_float(tf32_rna(W[k * 1024 + ci0 * 32 + co0]));
    w4.y = __uint_as_float(tf32_rna(W[k * 1024 + ci1 * 32 + co0]));
    w4.z = __uint_as_float(tf32_rna(W[k * 1024 + ci0 * 32 + co1]));
    w4.w = __uint_as_float(tf32_rna(W[k * 1024 + ci1 * 32 + co1]));
    ((float4*)dst)[k * 256 + t] = w4;
}

// ---------------------------------------------------------------------------
// Elementwise tf32 rounding pass (first layer's input).
// ---------------------------------------------------------------------------
__global__ __launch_bounds__(256)
void cvt_tf32_kernel(const float* __restrict__ x, float* __restrict__ y, int total4)
{
    for (int i = blockIdx.x * blockDim.x + threadIdx.x; i < total4;
         i += gridDim.x * blockDim.x) {
        float4 v = ((const float4*)x)[i];
        v.x = __uint_as_float(tf32_rna(v.x));
        v.y = __uint_as_float(tf32_rna(v.y));
        v.z = __uint_as_float(tf32_rna(v.z));
        v.w = __uint_as_float(tf32_rna(v.w));
        ((float4*)y)[i] = v;
    }
}

// ---------------------------------------------------------------------------
__device__ __forceinline__ void gather_pair(float4& g0, float4& g1,
                                            float4& g2, float4& g3,
                                            const float* __restrict__ in,
                                            int iA, int iB, int tg)
{
    g0 = make_float4(0.f, 0.f, 0.f, 0.f); g1 = g0; g2 = g0; g3 = g0;
    if (iA >= 0) {
        const float4* p = (const float4*)(in + (size_t)iA * 32) + tg * 2;
        g0 = __ldg(p); g1 = __ldg(p + 1);
    }
    if (iB >= 0) {
        const float4* p = (const float4*)(in + (size_t)iB * 32) + tg * 2;
        g2 = __ldg(p); g3 = __ldg(p + 1);
    }
}

// ---------------------------------------------------------------------------
// conv: block = 256 threads (8 warps), tile = 128 voxels x 32 out-channels.
// Warp tile M=16 (rows wid*16 .. wid*16+15). Gather for offset k+1 is issued
// before the MMAs of offset k (register double buffer) to hide L2 latency.
// ---------------------------------------------------------------------------
template<int KVOL>
__global__ __launch_bounds__(256, 3)
void conv_mma(const float* __restrict__ in, const int* __restrict__ nmap,
              const float* __restrict__ Wp, float* __restrict__ out,
              float* __restrict__ stats, int N)
{
    __shared__ float Red[8 * 64];

    const int tid  = threadIdx.x;
    const int wid  = tid >> 5, lane = tid & 31;
    const int gid  = lane >> 2, tg = lane & 3;
    const int mbase = blockIdx.x * 128;
    const int mrow  = mbase + wid * 16 + (lane & 15);
    const bool mv   = (mrow < N);

    float acc[4][4];
#pragma unroll
    for (int nt = 0; nt < 4; ++nt)
#pragma unroll
        for (int j = 0; j < 4; ++j) acc[nt][j] = 0.f;

    // prime the pipeline: gather(k=0) + idx(k=1)
    int idx0 = mv ? __ldg(nmap + mrow) : -1;
    float4 c0, c1, c2, c3;
    {
        int iA = __shfl_sync(0xffffffffu, idx0, gid);
        int iB = __shfl_sync(0xffffffffu, idx0, 8 + gid);
        gather_pair(c0, c1, c2, c3, in, iA, iB, tg);
    }
    int idxN = (KVOL > 1 && mv) ? __ldg(nmap + (size_t)N + mrow) : -1;

#pragma unroll
    for (int k = 0; k < KVOL; ++k) {
        // issue gather for k+1 (flies under the MMAs below)
        float4 n0, n1, n2, n3;
        if (k + 1 < KVOL) {
            int jA = __shfl_sync(0xffffffffu, idxN, gid);
            int jB = __shfl_sync(0xffffffffu, idxN, 8 + gid);
            gather_pair(n0, n1, n2, n3, in, jA, jB, tg);
        }
        idxN = (k + 2 < KVOL && mv) ? __ldg(nmap + (size_t)(k + 2) * N + mrow) : -1;

        // fragments from current gather (values already tf32-rounded)
        u32 A0[4] = { __float_as_uint(c0.x), __float_as_uint(c0.z), __float_as_uint(c1.x), __float_as_uint(c1.z) };
        u32 A2[4] = { __float_as_uint(c0.y), __float_as_uint(c0.w), __float_as_uint(c1.y), __float_as_uint(c1.w) };
        u32 A1[4] = { __float_as_uint(c2.x), __float_as_uint(c2.z), __float_as_uint(c3.x), __float_as_uint(c3.z) };
        u32 A3[4] = { __float_as_uint(c2.y), __float_as_uint(c2.w), __float_as_uint(c3.y), __float_as_uint(c3.w) };

        const float4* wb = (const float4*)Wp + (size_t)k * 256 + lane;
#pragma unroll
        for (int kt = 0; kt < 4; ++kt) {
#pragma unroll
            for (int ntp = 0; ntp < 2; ++ntp) {
                float4 w = __ldg(wb + kt * 64 + ntp * 32);
                u32 b00 = __float_as_uint(w.x), b01 = __float_as_uint(w.y);
                u32 b10 = __float_as_uint(w.z), b11 = __float_as_uint(w.w);
                MMA_TF32(acc[2 * ntp + 0], A0[kt], A1[kt], A2[kt], A3[kt], b00, b01);
                MMA_TF32(acc[2 * ntp + 1], A0[kt], A1[kt], A2[kt], A3[kt], b10, b11);
            }
        }
        c0 = n0; c1 = n1; c2 = n2; c3 = n3;
    }

    // ---- epilogue: store + fused BN stats ----
    const int r0 = mbase + wid * 16 + gid;
    const int r1 = r0 + 8;
#pragma unroll
    for (int nt = 0; nt < 4; ++nt) {
        int c = nt * 8 + tg * 2;
        if (r0 < N) *(float2*)(out + (size_t)r0 * 32 + c) = make_float2(acc[nt][0], acc[nt][1]);
        if (r1 < N) *(float2*)(out + (size_t)r1 * 32 + c) = make_float2(acc[nt][2], acc[nt][3]);
    }

    float s[4][2], q[4][2];
#pragma unroll
    for (int nt = 0; nt < 4; ++nt)
#pragma unroll
        for (int j = 0; j < 2; ++j) {
            float v0 = acc[nt][j], v1 = acc[nt][2 + j];
            s[nt][j] = v0 + v1;
            q[nt][j] = v0 * v0 + v1 * v1;
        }
#pragma unroll
    for (int off = 4; off < 32; off <<= 1)
#pragma unroll
        for (int nt = 0; nt < 4; ++nt)
#pragma unroll
            for (int j = 0; j < 2; ++j) {
                s[nt][j] += __shfl_xor_sync(0xffffffffu, s[nt][j], off);
                q[nt][j] += __shfl_xor_sync(0xffffffffu, q[nt][j], off);
            }
    if (lane < 4) {
#pragma unroll
        for (int nt = 0; nt < 4; ++nt)
#pragma unroll
            for (int j = 0; j < 2; ++j) {
                int c = nt * 8 + tg * 2 + j;
                Red[wid * 64 + c]      = s[nt][j];
                Red[wid * 64 + 32 + c] = q[nt][j];
            }
    }
    __syncthreads();
    if (tid < 64) {
        int plane = tid >> 5, c = tid & 31;
        float v = 0.f;
#pragma unroll
        for (int i = 0; i < 8; ++i) v += Red[i * 64 + plane * 32 + c];
        atomicAdd(stats + plane * 32 + c, v);
    }
}

// ---------------------------------------------------------------------------
// BN + ELU. round_tf32 != 0 -> output rounded to tf32 for the next conv.
// ---------------------------------------------------------------------------
__global__ __launch_bounds__(256)
void bnelu_kernel(const float* __restrict__ x, float* __restrict__ y,
                  const float* __restrict__ stats,
                  const float* __restrict__ gamma, const float* __restrict__ beta,
                  int N, int round_tf32)
{
    __shared__ float sc[32], sh[32];
    if (threadIdx.x < 32) {
        int c = threadIdx.x;
        float inv  = 1.0f / (float)N;
        float mean = stats[c] * inv;
        float var  = stats[32 + c] * inv - mean * mean;
        float sfac = rsqrtf(var + EPS) * gamma[c];
        sc[c] = sfac;
        sh[c] = beta[c] - mean * sfac;
    }
    __syncthreads();
    const int total4 = N * 8;
    for (int i = blockIdx.x * blockDim.x + threadIdx.x; i < total4;
         i += gridDim.x * blockDim.x) {
        float4 v = ((const float4*)x)[i];
        int c = (i * 4) & 31;
        float z;
        z = v.x * sc[c + 0] + sh[c + 0]; v.x = (z > 0.f) ? z : expm1f(z);
        z = v.y * sc[c + 1] + sh[c + 1]; v.y = (z > 0.f) ? z : expm1f(z);
        z = v.z * sc[c + 2] + sh[c + 2]; v.z = (z > 0.f) ? z : expm1f(z);
        z = v.w * sc[c + 3] + sh[c + 3]; v.w = (z > 0.f) ? z : expm1f(z);
        if (round_tf32) {
            v.x = __uint_as_float(tf32_rna(v.x));
            v.y = __uint_as_float(tf32_rna(v.y));
            v.z = __uint_as_float(tf32_rna(v.z));
            v.w = __uint_as_float(tf32_rna(v.w));
        }
        ((float4*)y)[i] = v;
    }
}

// ---------------------------------------------------------------------------
extern "C" void kernel_launch(void* const* d_in, const int* in_sizes, int n_in,
                              void* d_out, int out_size)
{
    const float* feats = (const float*)d_in[0];
    const float* W1    = (const float*)d_in[1];
    const float* g1    = (const float*)d_in[2];
    const float* b1    = (const float*)d_in[3];
    const float* W2    = (const float*)d_in[4];
    const float* g2    = (const float*)d_in[5];
    const float* b2    = (const float*)d_in[6];
    const float* W3    = (const float*)d_in[7];
    const float* g3    = (const float*)d_in[8];
    const float* b3    = (const float*)d_in[9];
    const int*   nmap3 = (const int*)d_in[10];
    const int*   nmap2 = (const int*)d_in[11];

    const int N = in_sizes[0] / 32;
    const int ntiles = (N + 127) / 128;

    float *bufA, *bufB, *bufC, *stats, *Wp;
    cudaGetSymbolAddress((void**)&bufA,  g_bufA);
    cudaGetSymbolAddress((void**)&bufB,  g_bufB);
    cudaGetSymbolAddress((void**)&bufC,  g_bufC);
    cudaGetSymbolAddress((void**)&stats, g_stats);
    cudaGetSymbolAddress((void**)&Wp,    g_Wp);

    cudaMemsetAsync(stats, 0, 3 * 64 * sizeof(float), 0);
    prep_weights<<<27, 256>>>(W1, Wp + 0 * 1024);
    prep_weights<<< 8, 256>>>(W2, Wp + 27 * 1024);
    prep_weights<<<27, 256>>>(W3, Wp + 35 * 1024);
    cvt_tf32_kernel<<<1024, 256>>>(feats, bufC, N * 8);

    conv_mma<27><<<ntiles, 256>>>(bufC, nmap3, Wp + 0 * 1024, bufA, stats + 0, N);
    bnelu_kernel<<<2048, 256>>>(bufA, bufA, stats + 0, g1, b1, N, 1);

    conv_mma<8><<<ntiles, 256>>>(bufA, nmap2, Wp + 27 * 1024, bufB, stats + 64, N);
    bnelu_kernel<<<2048, 256>>>(bufB, bufB, stats + 64, g2, b2, N, 1);

    conv_mma<27><<<ntiles, 256>>>(bufB, nmap3, Wp + 35 * 1024, bufA, stats + 128, N);
    bnelu_kernel<<<2048, 256>>>(bufA, (float*)d_out, stats + 128, g3, b3, N, 0);
}